// round 5
// baseline (speedup 1.0000x reference)
#include <cuda_runtime.h>
#include <math.h>

#define KN 32
#define KC 64
#define KT 400
#define KV 27
#define KS 2

typedef unsigned long long u64;

// ---------------- device scratch ----------------
__device__ float g_part[100 * KN * KS * KV * KV];   // 100 4-t chunks
__device__ float g_att [KN * KS * KV * KV];
__device__ float g_y4  [KN * KC * KT * KV];

__device__ __forceinline__ float lrelu(float x) { return x > 0.f ? x : 0.1f * x; }

__device__ __forceinline__ void ffma2(u64& d, u64 a, u64 b) {
  asm("fma.rn.f32x2 %0, %1, %2, %0;" : "+l"(d) : "l"(a), "l"(b));
}
__device__ __forceinline__ u64 bcast2(float w) {
  u64 r; asm("mov.b64 %0, {%1, %1};" : "=l"(r) : "f"(w)); return r;
}
__device__ __forceinline__ float2 unpk(u64 v) {
  float2 f; asm("mov.b64 {%0, %1}, %2;" : "=f"(f.x), "=f"(f.y) : "l"(v)); return f;
}

// ============================================================================
// Kernel A: per (4-t chunk, n) CTA, both s at once. 224 threads, 3 CTAs/SM.
// rows 0..15 q_s0 | 16..31 q_s1 | 32..47 k_s0 | 48..63 k_s1 (= W_in row order)
// Ys/QKs cols: col = u*4+tt, u padded to 28 (112 cols).
// smem: WQKT[64k][64r]@0 (4096) | BQK@4096 (64) | Ys@4160 (7168) | QKs@11328 (7168)
// total 18496 f = 73984 B
// ============================================================================
__global__ void __launch_bounds__(224, 3)
kA(const float* __restrict__ x, const float* __restrict__ pe,
   const float* __restrict__ W_in, const float* __restrict__ b_in) {
  extern __shared__ float sm[];
  const int WQ = 0, BQ = 4096, YSo = 4160, QKo = 11328;
  const int tid = threadIdx.x;
  const int chunk = blockIdx.x, n = blockIdx.y;
  const int t0 = chunk * 4;

  for (int j = tid; j < 4096; j += 224) {
    int k = j >> 6, r = j & 63;
    sm[WQ + k * 64 + r] = W_in[r * 64 + k];
  }
  if (tid < 64) sm[BQ + tid] = b_in[tid];
  for (int j = tid; j < 7168; j += 224) {
    int c = j / 112, col = j % 112, u = col >> 2, tt = col & 3;
    sm[YSo + j] = (u < 27)
        ? x[((n * 64 + c) * 400 + t0 + tt) * 27 + u] + pe[(c * 400 + t0 + tt) * 27 + u]
        : 0.f;
  }
  __syncthreads();

  // QK GEMM: 64 rows x 112 cols, K=64. Thread: 4 rows x 8 cols.
  {
    const int rg = tid / 14, cg = tid % 14;
    u64 acc[16];
    #pragma unroll
    for (int i = 0; i < 16; ++i) acc[i] = 0ull;
    #pragma unroll 4
    for (int k = 0; k < 64; ++k) {
      float4 wa = *(const float4*)&sm[WQ + k * 64 + rg * 4];
      ulonglong2 ya = *(const ulonglong2*)&sm[YSo + k * 112 + cg * 8];
      ulonglong2 yb = *(const ulonglong2*)&sm[YSo + k * 112 + cg * 8 + 4];
      u64 w;
      w = bcast2(wa.x); ffma2(acc[0],  w, ya.x); ffma2(acc[1],  w, ya.y); ffma2(acc[2],  w, yb.x); ffma2(acc[3],  w, yb.y);
      w = bcast2(wa.y); ffma2(acc[4],  w, ya.x); ffma2(acc[5],  w, ya.y); ffma2(acc[6],  w, yb.x); ffma2(acc[7],  w, yb.y);
      w = bcast2(wa.z); ffma2(acc[8],  w, ya.x); ffma2(acc[9],  w, ya.y); ffma2(acc[10], w, yb.x); ffma2(acc[11], w, yb.y);
      w = bcast2(wa.w); ffma2(acc[12], w, ya.x); ffma2(acc[13], w, ya.y); ffma2(acc[14], w, yb.x); ffma2(acc[15], w, yb.y);
    }
    #pragma unroll
    for (int r = 0; r < 4; ++r) {
      int row = rg * 4 + r;
      float b = sm[BQ + row];
      float2 A0 = unpk(acc[r * 4 + 0]);
      float2 A1 = unpk(acc[r * 4 + 1]);
      float2 A2 = unpk(acc[r * 4 + 2]);
      float2 A3 = unpk(acc[r * 4 + 3]);
      *(float4*)&sm[QKo + row * 112 + cg * 8] =
          make_float4(A0.x + b, A0.y + b, A1.x + b, A1.y + b);
      *(float4*)&sm[QKo + row * 112 + cg * 8 + 4] =
          make_float4(A2.x + b, A2.y + b, A3.x + b, A3.y + b);
    }
  }
  __syncthreads();

  // Gram: thread = (su = tid/4 in 0..53, vg = tid%4), v = vg*7 + 0..6.
  if (tid < 216) {
    const int su = tid >> 2, vg = tid & 3;
    const int s = su / 27, u = su % 27;
    float4 q[16];
    #pragma unroll
    for (int c = 0; c < 16; ++c)
      q[c] = *(const float4*)&sm[QKo + (s * 16 + c) * 112 + u * 4];
    const int base = (chunk * 64 + n * 2 + s) * 729 + u * 27;
    #pragma unroll
    for (int jj = 0; jj < 7; ++jj) {
      int v = vg * 7 + jj;
      if (v < 27) {
        float g = 0.f;
        #pragma unroll 4
        for (int c = 0; c < 16; ++c) {
          float4 kk = *(const float4*)&sm[QKo + (32 + s * 16 + c) * 112 + v * 4];
          g += q[c].x * kk.x + q[c].y * kk.y + q[c].z * kk.z + q[c].w * kk.w;
        }
        g_part[base + v] = g;
      }
    }
  }
}

// ============================================================================
// Kernel B: reduce 100 partials, tanh scale.
// ============================================================================
__global__ void kB(const float* __restrict__ alphas, const float* __restrict__ att0) {
  int idx = blockIdx.x * 256 + threadIdx.x;
  if (idx >= KN * KS * 729) return;
  int p = idx % 729;
  int s = (idx / 729) & 1;
  float sum = 0.f;
  #pragma unroll 10
  for (int ch = 0; ch < 100; ++ch) sum += g_part[ch * 46656 + idx];
  g_att[idx] = tanhf(sum * (1.0f / 6400.0f)) * alphas[s] + att0[s * 729 + p];
}

// ============================================================================
// Kernel C: per (n, 4-t tile), 224 threads, 3 CTAs/SM. cols = tt*28+v (112).
// smem: WB[32][64]@0 (2048) | ATT@2048 (1512) | CAO@3560 CBO@3624 CAF@3688
//       CBF@3752 | XS@3816 (7168) | YB@10984 (7168)  total 18152 f = 72608 B
// ============================================================================
__device__ __forceinline__ void kc_gemm32(const float* sm, int YB, int kbase,
                                          int og, int cg, u64* acc) {
  #pragma unroll 4
  for (int k = 0; k < 32; ++k) {
    const float* wr = &sm[k * 64 + og * 8];
    float4 wa = *(const float4*)wr;
    float4 wb = *(const float4*)(wr + 4);
    ulonglong2 y = *(const ulonglong2*)&sm[YB + (kbase + k) * 112 + cg * 4];
    u64 w;
    w = bcast2(wa.x); ffma2(acc[0],  w, y.x); ffma2(acc[1],  w, y.y);
    w = bcast2(wa.y); ffma2(acc[2],  w, y.x); ffma2(acc[3],  w, y.y);
    w = bcast2(wa.z); ffma2(acc[4],  w, y.x); ffma2(acc[5],  w, y.y);
    w = bcast2(wa.w); ffma2(acc[6],  w, y.x); ffma2(acc[7],  w, y.y);
    w = bcast2(wb.x); ffma2(acc[8],  w, y.x); ffma2(acc[9],  w, y.y);
    w = bcast2(wb.y); ffma2(acc[10], w, y.x); ffma2(acc[11], w, y.y);
    w = bcast2(wb.z); ffma2(acc[12], w, y.x); ffma2(acc[13], w, y.y);
    w = bcast2(wb.w); ffma2(acc[14], w, y.x); ffma2(acc[15], w, y.y);
  }
}

__device__ __forceinline__ void kc_y2(float* sm, int ATT, int XS, int YB,
                                      int S, int vq, int cq) {
  float a0r[27], a1r[27];
  const int v0 = vq * 2, v1 = vq * 2 + 1;
  #pragma unroll
  for (int u = 0; u < 27; ++u) {
    a0r[u] = sm[ATT + S * 756 + u * 28 + v0];
    a1r[u] = sm[ATT + S * 756 + u * 28 + v1];
  }
  #pragma unroll
  for (int ci = 0; ci < 4; ++ci) {
    const int c = cq * 4 + ci;
    const float* xr = &sm[XS + c * 112];
    #pragma unroll
    for (int tt = 0; tt < 4; ++tt) {
      float s0 = 0.f, s1 = 0.f;
      #pragma unroll
      for (int u = 0; u < 27; ++u) {
        float xv = xr[tt * 28 + u];
        s0 += xv * a0r[u]; s1 += xv * a1r[u];
      }
      sm[YB + c * 112 + tt * 28 + v0] = s0;
      sm[YB + c * 112 + tt * 28 + v1] = s1;
    }
  }
}

__global__ void __launch_bounds__(224, 3)
kC(const float* __restrict__ x,
   const float* __restrict__ W_out, const float* __restrict__ b_out,
   const float* __restrict__ gm_out, const float* __restrict__ be_out,
   const float* __restrict__ m_out, const float* __restrict__ v_out,
   const float* __restrict__ W_ff, const float* __restrict__ b_ff,
   const float* __restrict__ gm_ff, const float* __restrict__ be_ff,
   const float* __restrict__ m_ff, const float* __restrict__ v_ff) {
  extern __shared__ float sm[];
  const int ATT = 2048, CAO = 3560, CBO = 3624, CAF = 3688, CBF = 3752;
  const int XS = 3816, YB = 10984;
  const int tid = threadIdx.x;
  const int n = blockIdx.y;
  const int t0 = blockIdx.x * 4;

  for (int j = tid; j < 7168; j += 224) {
    int c = j / 112, col = j % 112, tt = col / 28, v = col % 28;
    sm[XS + j] = (v < 27) ? x[((n * 64 + c) * 400 + t0 + tt) * 27 + v] : 0.f;
  }
  for (int j = tid; j < 1512; j += 224) {
    int s = j / 756, r = j % 756, u = r / 28, v = r % 28;
    sm[ATT + j] = (v < 27) ? g_att[(n * 2 + s) * 729 + u * 27 + v] : 0.f;
  }
  for (int j = tid; j < 2048; j += 224) {      // W_out s0, c 0..31
    int k = j >> 6, o = j & 63;
    sm[j] = W_out[o * 128 + k];
  }
  if (tid < 64) {
    float a = gm_out[tid] * rsqrtf(v_out[tid] + 1e-5f);
    sm[CAO + tid] = a;
    sm[CBO + tid] = (b_out[tid] - m_out[tid]) * a + be_out[tid];
    float af = gm_ff[tid] * rsqrtf(v_ff[tid] + 1e-5f);
    sm[CAF + tid] = af;
    sm[CBF + tid] = (b_ff[tid] - m_ff[tid]) * af + be_ff[tid];
  }
  __syncthreads();

  const int vq = tid / 16, cq = tid % 16;
  const int og = tid / 28, cg = tid % 28;
  u64 acc[16];
  #pragma unroll
  for (int i = 0; i < 16; ++i) acc[i] = 0ull;

  kc_y2(sm, ATT, XS, YB, 0, vq, cq);
  __syncthreads();
  kc_gemm32(sm, YB, 0, og, cg, acc);
  __syncthreads();
  for (int j = tid; j < 2048; j += 224) {      // W_out s0, c 32..63
    int k = j >> 6, o = j & 63;
    sm[j] = W_out[o * 128 + 32 + k];
  }
  __syncthreads();
  kc_gemm32(sm, YB, 32, og, cg, acc);
  __syncthreads();
  for (int j = tid; j < 2048; j += 224) {      // W_out s1, c 0..31
    int k = j >> 6, o = j & 63;
    sm[j] = W_out[o * 128 + 64 + k];
  }
  kc_y2(sm, ATT, XS, YB, 1, vq, cq);
  __syncthreads();
  kc_gemm32(sm, YB, 0, og, cg, acc);
  __syncthreads();
  for (int j = tid; j < 2048; j += 224) {      // W_out s1, c 32..63
    int k = j >> 6, o = j & 63;
    sm[j] = W_out[o * 128 + 96 + k];
  }
  __syncthreads();
  kc_gemm32(sm, YB, 32, og, cg, acc);
  __syncthreads();

  // epilogue 1: y3 -> YB ; load W_ff chunk 0
  for (int j = tid; j < 2048; j += 224) {
    int k = j >> 6, o = j & 63;
    sm[j] = W_ff[o * 64 + k];
  }
  #pragma unroll
  for (int jo = 0; jo < 8; ++jo) {
    int o = og * 8 + jo;
    float a = sm[CAO + o], b = sm[CBO + o];
    float2 A0 = unpk(acc[jo * 2]);
    float2 A1 = unpk(acc[jo * 2 + 1]);
    int base = cg * 4;
    float r0 = lrelu(sm[XS + o * 112 + base + 0] + A0.x * a + b);
    float r1 = lrelu(sm[XS + o * 112 + base + 1] + A0.y * a + b);
    float r2 = lrelu(sm[XS + o * 112 + base + 2] + A1.x * a + b);
    float r3 = lrelu(sm[XS + o * 112 + base + 3] + A1.y * a + b);
    *(float4*)&sm[YB + o * 112 + base] = make_float4(r0, r1, r2, r3);
  }
  #pragma unroll
  for (int i = 0; i < 16; ++i) acc[i] = 0ull;
  __syncthreads();

  kc_gemm32(sm, YB, 0, og, cg, acc);
  __syncthreads();
  for (int j = tid; j < 2048; j += 224) {
    int k = j >> 6, o = j & 63;
    sm[j] = W_ff[o * 64 + 32 + k];
  }
  __syncthreads();
  kc_gemm32(sm, YB, 32, og, cg, acc);

  // epilogue 2: y4 -> global
  #pragma unroll
  for (int jo = 0; jo < 8; ++jo) {
    int o = og * 8 + jo;
    float a = sm[CAF + o], b = sm[CBF + o];
    float2 A0 = unpk(acc[jo * 2]);
    float2 A1 = unpk(acc[jo * 2 + 1]);
    float rv[4] = {A0.x, A0.y, A1.x, A1.y};
    #pragma unroll
    for (int e = 0; e < 4; ++e) {
      int col = cg * 4 + e;
      int tt = col / 28, v = col % 28;
      if (v < 27) {
        float r = lrelu(sm[XS + o * 112 + col] + rv[e] * a + b);
        g_y4[((long)(n * 64 + o) * 400 + t0 + tt) * 27 + v] = r;
      }
    }
  }
}

// ============================================================================
// Kernel D: temporal conv, 224 threads, 3 CTAs/SM, W+YS phased in 32-i chunks.
// smem: WB[96][64]@0 (6144) | YS[32][280]@6144 (8960) | CAT@15104 CBT@15168
// total 15232 f = 60928 B
// ============================================================================
__global__ void __launch_bounds__(224, 3)
kD(const float* __restrict__ W_t, const float* __restrict__ b_t,
   const float* __restrict__ gm_t, const float* __restrict__ be_t,
   const float* __restrict__ m_t, const float* __restrict__ v_t,
   float* __restrict__ out) {
  extern __shared__ float sm[];
  const int YS = 6144, CAT = 15104, CBT = 15168;
  const int tid = threadIdx.x;
  const int n = blockIdx.y;
  const int t0 = blockIdx.x * 8;

  if (tid < 64) {
    float a = gm_t[tid] * rsqrtf(v_t[tid] + 1e-5f);
    sm[CAT + tid] = a;
    sm[CBT + tid] = (b_t[tid] - m_t[tid]) * a + be_t[tid];
  }

  const int og = tid / 28, cg = tid % 28;
  u64 acc[32];
  #pragma unroll
  for (int i = 0; i < 32; ++i) acc[i] = 0ull;

  for (int p = 0; p < 2; ++p) {
    __syncthreads();
    for (int j = tid; j < 6144; j += 224) {
      int r = j >> 6, o = j & 63;          // r = il*3+kk
      sm[r * 64 + o] = W_t[o * 192 + p * 96 + r];
    }
    for (int j = tid; j < 8960; j += 224) {
      int il = j / 280, rr = j % 280, tl = rr / 28, v = rr % 28;
      int t = t0 - 1 + tl;
      sm[YS + j] = (v < 27 && t >= 0 && t < 400)
                   ? g_y4[((long)(n * 64 + p * 32 + il) * 400 + t) * 27 + v] : 0.f;
    }
    __syncthreads();

    #pragma unroll 2
    for (int il = 0; il < 32; ++il) {
      #pragma unroll
      for (int kk = 0; kk < 3; ++kk) {
        const float* wr = &sm[(il * 3 + kk) * 64 + og * 8];
        float4 wa = *(const float4*)wr;
        float4 wb = *(const float4*)(wr + 4);
        ulonglong2 ya = *(const ulonglong2*)&sm[YS + il * 280 + kk * 28 + cg * 4];
        ulonglong2 yb = *(const ulonglong2*)&sm[YS + il * 280 + kk * 28 + 112 + cg * 4];
        u64 w;
        w = bcast2(wa.x); ffma2(acc[0],  w, ya.x); ffma2(acc[1],  w, ya.y); ffma2(acc[2],  w, yb.x); ffma2(acc[3],  w, yb.y);
        w = bcast2(wa.y); ffma2(acc[4],  w, ya.x); ffma2(acc[5],  w, ya.y); ffma2(acc[6],  w, yb.x); ffma2(acc[7],  w, yb.y);
        w = bcast2(wa.z); ffma2(acc[8],  w, ya.x); ffma2(acc[9],  w, ya.y); ffma2(acc[10], w, yb.x); ffma2(acc[11], w, yb.y);
        w = bcast2(wa.w); ffma2(acc[12], w, ya.x); ffma2(acc[13], w, ya.y); ffma2(acc[14], w, yb.x); ffma2(acc[15], w, yb.y);
        w = bcast2(wb.x); ffma2(acc[16], w, ya.x); ffma2(acc[17], w, ya.y); ffma2(acc[18], w, yb.x); ffma2(acc[19], w, yb.y);
        w = bcast2(wb.y); ffma2(acc[20], w, ya.x); ffma2(acc[21], w, ya.y); ffma2(acc[22], w, yb.x); ffma2(acc[23], w, yb.y);
        w = bcast2(wb.z); ffma2(acc[24], w, ya.x); ffma2(acc[25], w, ya.y); ffma2(acc[26], w, yb.x); ffma2(acc[27], w, yb.y);
        w = bcast2(wb.w); ffma2(acc[28], w, ya.x); ffma2(acc[29], w, ya.y); ffma2(acc[30], w, yb.x); ffma2(acc[31], w, yb.y);
      }
    }
  }

  // epilogue: residual re-read from gmem
  #pragma unroll
  for (int jo = 0; jo < 8; ++jo) {
    int o = og * 8 + jo;
    float a = sm[CAT + o], b = sm[CBT + o];
    #pragma unroll
    for (int h = 0; h < 2; ++h) {
      float2 A0 = unpk(acc[jo * 4 + h * 2]);
      float2 A1 = unpk(acc[jo * 4 + h * 2 + 1]);
      float rv[4] = {A0.x, A0.y, A1.x, A1.y};
      int base = h * 112 + cg * 4;
      #pragma unroll
      for (int e = 0; e < 4; ++e) {
        int col = base + e;
        int tt = col / 28, v = col % 28;
        if (v < 27) {
          long idx = ((long)(n * 64 + o) * 400 + t0 + tt) * 27 + v;
          float y = g_y4[idx];
          out[idx] = lrelu(y + rv[e] * a + b);
        }
      }
    }
  }
}

// ============================================================================
extern "C" void kernel_launch(void* const* d_in, const int* in_sizes, int n_in,
                              void* d_out, int out_size) {
  const float* x      = (const float*)d_in[0];
  const float* pe     = (const float*)d_in[1];
  const float* W_in   = (const float*)d_in[2];
  const float* b_in   = (const float*)d_in[3];
  const float* alphas = (const float*)d_in[4];
  const float* att0   = (const float*)d_in[5];
  const float* W_out  = (const float*)d_in[6];
  const float* b_out  = (const float*)d_in[7];
  const float* g_out  = (const float*)d_in[8];
  const float* be_out = (const float*)d_in[9];
  const float* m_out  = (const float*)d_in[10];
  const float* v_out  = (const float*)d_in[11];
  const float* W_ff   = (const float*)d_in[12];
  const float* b_ff   = (const float*)d_in[13];
  const float* g_ff   = (const float*)d_in[14];
  const float* be_ff  = (const float*)d_in[15];
  const float* m_ff   = (const float*)d_in[16];
  const float* v_ff   = (const float*)d_in[17];
  const float* W_t    = (const float*)d_in[18];
  const float* b_t    = (const float*)d_in[19];
  const float* g_t    = (const float*)d_in[20];
  const float* be_t   = (const float*)d_in[21];
  const float* m_t    = (const float*)d_in[22];
  const float* v_t    = (const float*)d_in[23];
  float* out = (float*)d_out;

  cudaFuncSetAttribute(kA, cudaFuncAttributeMaxDynamicSharedMemorySize, 73984);
  cudaFuncSetAttribute(kC, cudaFuncAttributeMaxDynamicSharedMemorySize, 72608);
  cudaFuncSetAttribute(kD, cudaFuncAttributeMaxDynamicSharedMemorySize, 60928);

  kA<<<dim3(100, 32), 224, 73984>>>(x, pe, W_in, b_in);
  kB<<<(KN * KS * 729 + 255) / 256, 256>>>(alphas, att0);
  kC<<<dim3(100, 32), 224, 72608>>>(x, W_out, b_out, g_out, be_out, m_out, v_out,
                                    W_ff, b_ff, g_ff, be_ff, m_ff, v_ff);
  kD<<<dim3(50, 32), 224, 60928>>>(W_t, b_t, g_t, be_t, m_t, v_t, out);
}